// round 11
// baseline (speedup 1.0000x reference)
#include <cuda_runtime.h>
#include <cstddef>

// GRU_AE fused, layer-pipelined, K=16 steps per barrier interval (processed as
// 2 half-passes of 8), 2 batches/block, 256 blocks (2 blocks/SM, single wave).
//   wid 0..3: layer warps (parity-staggered map so co-resident blocks put
//             different layers on the same SMSP); wid 4: FC + x loader.
// All gate dots use fma.rn.f32x2 (2 batches = 1 packed pair). h-side weights
// live in registers; {w,w} packed per use via volatile mov (alu pipe, overlaps
// fma pipe). x-phase accumulators pass to the serial h-phase via lane-private
// smem scratch (keeps the h j-loop rolled -> bounded registers).

#define T_LEN 2048
#define NTHR  160
#define NBLK  256    // * 2 batches = 512
#define KS    16
#define HKS   8      // half-interval
#define NINT  (T_LEN / KS + 4)   // 132

#define BAR() asm volatile("bar.sync 0, %0;" :: "n"(NTHR) : "memory")
#define PACK2(d, s)      asm("mov.b64 %0, {%1, %1};" : "=l"(d) : "f"(s))
#define PACK2V(d, s)     asm volatile("mov.b64 %0, {%1, %1};" : "=l"(d) : "f"(s))
#define UNPACK2(a, b, s) asm("mov.b64 {%0, %1}, %2;" : "=f"(a), "=f"(b) : "l"(s))
#define FMA2(acc, w, v)  asm("fma.rn.f32x2 %0, %1, %2, %0;" : "+l"(acc) : "l"(w), "l"(v))

typedef unsigned long long u64;

struct Smem {
    float2 xb [2][KS][32];
    float2 hb1[2][KS][32];
    float2 hb2[2][KS][32];
    float2 hb3[2][KS][32];
    float2 hb4[2][KS][32];
    float2 gx [4][3][HKS][32];  // per-layer-warp x-accum scratch (lane-private)
    float  wtx1[3][32][30];     // x-side weights, transposed [gate][col][unit]
    float  wtx2[3][30][15];
    float  wtx3[3][15][30];
    float  wtx4[3][30][16];
};

static __device__ __forceinline__ float sigm(float x) {
    return __fdividef(1.0f, 1.0f + __expf(-x));
}
static __device__ __forceinline__ float tanh_f(float x) {
    float e = __expf(2.0f * x);
    return 1.0f - __fdividef(2.0f, e + 1.0f);
}

// Stage x-side weights transposed: dst[(g*IN + c)*HID + u] = wih[(g*HID+u)*IN + c]
template <int IN, int HID>
static __device__ void stage_x(float* dst, const float* __restrict__ wih, int tid) {
    for (int i = tid; i < 3 * IN * HID; i += NTHR) {
        int u = i % HID;
        int gc = i / HID;
        int c = gc % IN;
        int g = gc / IN;
        dst[(g * IN + c) * HID + u] = wih[(g * HID + u) * IN + c];
    }
}

template <int IN, int HID, int DELAY>
static __device__ void layer_warp(
    const float* __restrict__ wtx,      // smem [3][IN][HID]
    float2 (*gx)[HKS][32],              // smem scratch [3][HKS][32] (this warp's)
    const float* __restrict__ whh,      // global [3H][H]
    const float* __restrict__ bih, const float* __restrict__ bhh,
    const float2 (*vb)[KS][32], float2 (*hb)[KS][32], int lane)
{
    const int hc = (lane < HID) ? lane : 0;

    // h-side weights into registers (own row of each gate).
    float wr[HID], wz[HID], wn[HID];
#pragma unroll
    for (int c = 0; c < HID; ++c) {
        wr[c] = __ldg(whh + (0 * HID + hc) * HID + c);
        wz[c] = __ldg(whh + (1 * HID + hc) * HID + c);
        wn[c] = __ldg(whh + (2 * HID + hc) * HID + c);
    }
    const float br = __ldg(bih + hc)           + __ldg(bhh + hc);
    const float bz = __ldg(bih + HID + hc)     + __ldg(bhh + HID + hc);
    const float bm = __ldg(bih + 2 * HID + hc);    // b_ih_n
    const float bn = __ldg(bhh + 2 * HID + hc);    // b_hh_n
    u64 pbr, pbz, pbm;
    PACK2(pbr, br); PACK2(pbz, bz); PACK2(pbm, bm);

    float2 hp = {0.f, 0.f};

    for (int m = 0; m < NINT; ++m) {
        const int p = m & 1;
        if (m >= DELAY && m < DELAY + T_LEN / KS) {
#pragma unroll 1
            for (int half = 0; half < 2; ++half) {
                const int j0 = half * HKS;
                // ---- x-phase: 8 independent steps, packed FFMA2 ----
                u64 axr[HKS], axz[HKS], axn[HKS];
#pragma unroll
                for (int j = 0; j < HKS; ++j) { axr[j] = pbr; axz[j] = pbz; axn[j] = pbm; }
#pragma unroll 4
                for (int c = 0; c < IN; ++c) {
                    u64 wrp, wzp, wnp;
                    float a = wtx[(0 * IN + c) * HID + hc];
                    float b = wtx[(1 * IN + c) * HID + hc];
                    float d = wtx[(2 * IN + c) * HID + hc];
                    PACK2(wrp, a); PACK2(wzp, b); PACK2(wnp, d);
#pragma unroll
                    for (int j = 0; j < HKS; ++j) {
                        u64 v2 = *(const u64*)&vb[1 - p][j0 + j][c];  // broadcast LDS.64
                        FMA2(axr[j], wrp, v2);
                        FMA2(axz[j], wzp, v2);
                        FMA2(axn[j], wnp, v2);
                    }
                }
#pragma unroll
                for (int j = 0; j < HKS; ++j) {     // lane-private scratch
                    *(u64*)&gx[0][j][lane] = axr[j];
                    *(u64*)&gx[1][j][lane] = axz[j];
                    *(u64*)&gx[2][j][lane] = axn[j];
                }
                // ---- h-phase: serial over the 8 steps (rolled j-loop) ----
#pragma unroll 1
                for (int j = 0; j < HKS; ++j) {
                    const int jj = j0 + j;
                    u64 ar = *(const u64*)&gx[0][j][lane];
                    u64 az = *(const u64*)&gx[1][j][lane];
                    u64 an; PACK2V(an, bn);
                    const float2* hv = (jj == 0) ? hb[1 - p][KS - 1] : hb[p][jj - 1];
#pragma unroll
                    for (int c = 0; c < HID; ++c) {
                        u64 h2 = *(const u64*)&hv[c];             // broadcast LDS.64
                        u64 t;
                        PACK2V(t, wr[c]); FMA2(ar, t, h2);
                        PACK2V(t, wz[c]); FMA2(az, t, h2);
                        PACK2V(t, wn[c]); FMA2(an, t, h2);
                    }
                    float arx, ary, azx, azy, anx, any_, mx, my;
                    UNPACK2(arx, ary, ar);
                    UNPACK2(azx, azy, az);
                    UNPACK2(anx, any_, an);
                    {
                        u64 m2 = *(const u64*)&gx[2][j][lane];
                        UNPACK2(mx, my, m2);
                    }
                    float rx = sigm(arx), ry = sigm(ary);
                    float zx = sigm(azx), zy = sigm(azy);
                    float nx = tanh_f(fmaf(rx, anx, mx));
                    float ny = tanh_f(fmaf(ry, any_, my));
                    float2 hn;
                    hn.x = nx + zx * (hp.x - nx);
                    hn.y = ny + zy * (hp.y - ny);
                    hp = hn;
                    if (lane < HID) hb[p][jj][lane] = hn;
                    __syncwarp();        // order STS before next step's LDS
                }
            }
        }
        BAR();                           // one barrier per 16 timesteps
    }
}

// Warp 4: FC for steps 16(m-4)+j + x loader for interval m+1.
static __device__ void fc_warp(
    const float* __restrict__ fcw, const float* __restrict__ fcb,
    const float* __restrict__ x,   float* __restrict__ out,
    int bbase, int lane,
    const float2 (*hb4)[KS][32], float2 (*xb)[KS][32])
{
    const int c10 = (lane < 10) ? lane : 0;
    float w[16];
#pragma unroll
    for (int c = 0; c < 16; ++c) w[c] = __ldg(fcw + c10 * 16 + c);
    const float bfc = __ldg(fcb + c10);

    for (int m = 0; m < NINT; ++m) {
        const int p = m & 1;
#pragma unroll 4
        for (int j = 0; j < KS; ++j) {
            int s = KS * (m + 1) + j;
            if (s < T_LEN) {
                size_t off = (size_t)s * 32 + lane;
                float2 xv;
                xv.x = __ldg(x + (size_t)(bbase + 0) * T_LEN * 32 + off);
                xv.y = __ldg(x + (size_t)(bbase + 1) * T_LEN * 32 + off);
                xb[p][j][lane] = xv;
            }
        }
        if (m >= 4) {
#pragma unroll 4
            for (int j = 0; j < KS; ++j) {
                int t = KS * (m - 4) + j;
                const float2* h4 = hb4[1 - p][j];
                float2 acc = make_float2(bfc, bfc);
#pragma unroll
                for (int c = 0; c < 16; ++c) {
                    float2 v = h4[c];
                    acc.x = fmaf(w[c], v.x, acc.x);
                    acc.y = fmaf(w[c], v.y, acc.y);
                }
                if (lane < 10) {
                    size_t base = ((size_t)bbase * 10 + lane) * T_LEN + t;
                    out[base]                      = acc.x;
                    out[base + 10 * (size_t)T_LEN] = acc.y;
                }
            }
        }
        BAR();
    }
}

__global__ void __launch_bounds__(NTHR, 2)
gru_ae_k16_kernel(const float* __restrict__ x,
                  const float* __restrict__ fcw,  const float* __restrict__ fcb,
                  const float* __restrict__ wih1, const float* __restrict__ whh1,
                  const float* __restrict__ bih1, const float* __restrict__ bhh1,
                  const float* __restrict__ wih2, const float* __restrict__ whh2,
                  const float* __restrict__ bih2, const float* __restrict__ bhh2,
                  const float* __restrict__ wih3, const float* __restrict__ whh3,
                  const float* __restrict__ bih3, const float* __restrict__ bhh3,
                  const float* __restrict__ wih4, const float* __restrict__ whh4,
                  const float* __restrict__ bih4, const float* __restrict__ bhh4,
                  float* __restrict__ out)
{
    extern __shared__ char raw[];
    Smem* sm = (Smem*)raw;

    const int tid   = threadIdx.x;
    const int wid   = tid >> 5;
    const int lane  = tid & 31;
    const int bbase = blockIdx.x * 2;
    const bool odd  = (blockIdx.x & 1) != 0;

    stage_x<32, 30>(&sm->wtx1[0][0][0], wih1, tid);
    stage_x<30, 15>(&sm->wtx2[0][0][0], wih2, tid);
    stage_x<15, 30>(&sm->wtx3[0][0][0], wih3, tid);
    stage_x<30, 16>(&sm->wtx4[0][0][0], wih4, tid);
    {
        float2 z2 = {0, 0};
        float2* bufs[5] = { &sm->xb[0][0][0], &sm->hb1[0][0][0], &sm->hb2[0][0][0],
                            &sm->hb3[0][0][0], &sm->hb4[0][0][0] };
#pragma unroll
        for (int b = 0; b < 5; ++b)
            for (int i = tid; i < 2 * KS * 32; i += NTHR) bufs[b][i] = z2;
    }
    __syncthreads();

    // Prelude: x steps 0..15 into xb[1] (interval 0 reads parity 1-p = 1).
    if (wid == 4) {
#pragma unroll
        for (int j = 0; j < KS; ++j) {
            size_t off = (size_t)j * 32 + lane;
            float2 xv;
            xv.x = __ldg(x + (size_t)(bbase + 0) * T_LEN * 32 + off);
            xv.y = __ldg(x + (size_t)(bbase + 1) * T_LEN * 32 + off);
            sm->xb[1][j][lane] = xv;
        }
    }
    __syncthreads();

    // Parity-staggered layer->warp map (SMSP = wid%4):
    //  even block: wid0=L2 wid1=L1 wid2=L3 wid3=L4
    //  odd  block: wid0=L4 wid1=L3 wid2=L2 wid3=L1
    if (wid == 4) {
        fc_warp(fcw, fcb, x, out, bbase, lane, sm->hb4, sm->xb);
    } else if ((!odd && wid == 1) || (odd && wid == 3)) {
        layer_warp<32, 30, 0>(&sm->wtx1[0][0][0], sm->gx[0], whh1, bih1, bhh1,
                              sm->xb,  sm->hb1, lane);
    } else if ((!odd && wid == 0) || (odd && wid == 2)) {
        layer_warp<30, 15, 1>(&sm->wtx2[0][0][0], sm->gx[1], whh2, bih2, bhh2,
                              sm->hb1, sm->hb2, lane);
    } else if ((!odd && wid == 2) || (odd && wid == 1)) {
        layer_warp<15, 30, 2>(&sm->wtx3[0][0][0], sm->gx[2], whh3, bih3, bhh3,
                              sm->hb2, sm->hb3, lane);
    } else {
        layer_warp<30, 16, 3>(&sm->wtx4[0][0][0], sm->gx[3], whh4, bih4, bhh4,
                              sm->hb3, sm->hb4, lane);
    }
}

extern "C" void kernel_launch(void* const* d_in, const int* in_sizes, int n_in,
                              void* d_out, int out_size) {
    (void)in_sizes; (void)n_in; (void)out_size;
    const float* x    = (const float*)d_in[0];
    const float* fcw  = (const float*)d_in[1];
    const float* fcb  = (const float*)d_in[2];
    const float* wih1 = (const float*)d_in[3];
    const float* whh1 = (const float*)d_in[4];
    const float* bih1 = (const float*)d_in[5];
    const float* bhh1 = (const float*)d_in[6];
    const float* wih2 = (const float*)d_in[7];
    const float* whh2 = (const float*)d_in[8];
    const float* bih2 = (const float*)d_in[9];
    const float* bhh2 = (const float*)d_in[10];
    const float* wih3 = (const float*)d_in[11];
    const float* whh3 = (const float*)d_in[12];
    const float* bih3 = (const float*)d_in[13];
    const float* bhh3 = (const float*)d_in[14];
    const float* wih4 = (const float*)d_in[15];
    const float* whh4 = (const float*)d_in[16];
    const float* bih4 = (const float*)d_in[17];
    const float* bhh4 = (const float*)d_in[18];
    float* out = (float*)d_out;

    cudaFuncSetAttribute(gru_ae_k16_kernel,
                         cudaFuncAttributeMaxDynamicSharedMemorySize,
                         (int)sizeof(Smem));

    gru_ae_k16_kernel<<<NBLK, NTHR, sizeof(Smem)>>>(
        x, fcw, fcb,
        wih1, whh1, bih1, bhh1,
        wih2, whh2, bih2, bhh2,
        wih3, whh3, bih3, bhh3,
        wih4, whh4, bih4, bhh4,
        out);
}